// round 1
// baseline (speedup 1.0000x reference)
#include <cuda_runtime.h>
#include <cstdint>
#include <math.h>

// Problem shape (fixed by the dataset)
#define BB 2048
#define CC 256
#define TT 512

// Scratch (allocations are forbidden; __device__ globals are the sanctioned path)
__device__ float g_FF[(size_t)BB * TT * CC];   // 1 GiB: FF[b][t][i]
__device__ float g_WfT[CC * CC];               // WfT[c][i] = Wf[i][c]
__device__ float g_WrT[CC * CC];               // WrT[j][i] = Wr[i][j]

// ---------------------------------------------------------------------------
// Tiny transpose of both weight matrices (256x256 each)
// ---------------------------------------------------------------------------
__global__ void transpose_kernel(const float* __restrict__ Wf,
                                 const float* __restrict__ Wr) {
    int idx = blockIdx.x * blockDim.x + threadIdx.x;   // 0 .. 65535
    int i = idx >> 8;
    int c = idx & 255;
    g_WfT[c * CC + i] = Wf[i * CC + c];
    g_WrT[c * CC + i] = Wr[i * CC + c];
}

// ---------------------------------------------------------------------------
// FF[b][t][i] = sum_c x[b][c][t] * WfT[c][i]
// Per batch b: M=T=512 (t), N=C=256 (i), K=C=256 (c).
// A[t][c] = x[b][c][t]  (contiguous along t -> coalesced tile loads)
// B[c][i] = WfT         (contiguous along i -> coalesced tile loads)
// Classic 64x64x16 tiled fp32 SGEMM, 4x4 register microtile, 256 threads.
// ---------------------------------------------------------------------------
__global__ void __launch_bounds__(256) gemm_kernel(const float* __restrict__ x) {
    const int BM = 64, BN = 64, BK = 16;
    __shared__ float As[BK][BM];   // As[k][m] = x[b][c0+k][t0+m]
    __shared__ float Bs[BK][BN];   // Bs[k][n] = WfT[c0+k][i0+n]

    int b  = blockIdx.z;
    int t0 = blockIdx.y * BM;
    int i0 = blockIdx.x * BN;
    int tid = threadIdx.x;

    int lk  = tid >> 4;            // 0..15 : k row for loads
    int lm4 = (tid & 15) * 4;      // 0..60 : float4 offset for loads
    int ty  = tid >> 4;            // 0..15 : m-group
    int tx  = tid & 15;            // 0..15 : n-group

    const float* xb = x + (size_t)b * CC * TT;

    float acc[4][4] = {};

    for (int c0 = 0; c0 < CC; c0 += BK) {
        *(float4*)&As[lk][lm4] =
            *(const float4*)&xb[(size_t)(c0 + lk) * TT + t0 + lm4];
        *(float4*)&Bs[lk][lm4] =
            *(const float4*)&g_WfT[(c0 + lk) * CC + i0 + lm4];
        __syncthreads();

#pragma unroll
        for (int k = 0; k < BK; k++) {
            float4 a  = *(const float4*)&As[k][ty * 4];
            float4 bq = *(const float4*)&Bs[k][tx * 4];
            float av[4] = {a.x, a.y, a.z, a.w};
            float bv[4] = {bq.x, bq.y, bq.z, bq.w};
#pragma unroll
            for (int mi = 0; mi < 4; mi++)
#pragma unroll
                for (int ni = 0; ni < 4; ni++)
                    acc[mi][ni] += av[mi] * bv[ni];
        }
        __syncthreads();
    }

    float* outp = g_FF + (size_t)b * TT * CC + (size_t)(t0 + ty * 4) * CC + i0 + tx * 4;
#pragma unroll
    for (int mi = 0; mi < 4; mi++) {
        float4 r = {acc[mi][0], acc[mi][1], acc[mi][2], acc[mi][3]};
        *(float4*)(outp + (size_t)mi * CC) = r;
    }
}

// ---------------------------------------------------------------------------
// Sequential LIF + WTA scan. One warp owns one batch row (fully independent).
// v[256] lives in 8 regs/lane; lane owns channels [8*lane, 8*lane+8).
// Recurrent term = gather of one WrT row (one-hot spike), coalesced.
// ---------------------------------------------------------------------------
__global__ void __launch_bounds__(256) scan_kernel(float* __restrict__ out) {
    const float DECAY = (float)(1.0 - 1.0 / 6.0);   // 1 - 1/tau
    const float VTH   = 3.0f;

    int w    = (int)((blockIdx.x * blockDim.x + threadIdx.x) >> 5);  // batch row
    int lane = threadIdx.x & 31;
    if (w >= BB) return;

    const float* ffb = g_FF + (size_t)w * TT * CC + lane * 8;

    float v[8];
#pragma unroll
    for (int j = 0; j < 8; j++) v[j] = 0.0f;

    int jprev = -1;   // channel of previous WTA spike, -1 = no spike

    for (int t = 0; t < TT; t++) {
        // feedforward input (streamed once from DRAM, coalesced float4s)
        float4 f0 = *(const float4*)(ffb + (size_t)t * CC);
        float4 f1 = *(const float4*)(ffb + (size_t)t * CC + 4);
        float f[8] = {f0.x, f0.y, f0.z, f0.w, f1.x, f1.y, f1.z, f1.w};

        // recurrent input: one-hot spike -> one row of WrT (warp-uniform branch)
        if (jprev >= 0) {
            const float4* wp = (const float4*)(g_WrT + jprev * CC + lane * 8);
            float4 r0 = wp[0];
            float4 r1 = wp[1];
            f[0] += r0.x; f[1] += r0.y; f[2] += r0.z; f[3] += r0.w;
            f[4] += r1.x; f[5] += r1.y; f[6] += r1.z; f[7] += r1.w;
        }

        // LIF charge (decay_input=False): v = v*decay + inp
#pragma unroll
        for (int j = 0; j < 8; j++) v[j] = v[j] * DECAY + f[j];

        // WTA: argmax over 256 channels, first-occurrence tie-break
        float m = v[0];
        int   mi = 0;
#pragma unroll
        for (int j = 1; j < 8; j++)
            if (v[j] > m) { m = v[j]; mi = j; }
        int gi = lane * 8 + mi;
#pragma unroll
        for (int off = 16; off > 0; off >>= 1) {
            float om = __shfl_xor_sync(0xFFFFFFFFu, m,  off);
            int   oi = __shfl_xor_sync(0xFFFFFFFFu, gi, off);
            if (om > m || (om == m && oi < gi)) { m = om; gi = oi; }
        }

        // spike_out (one-hot, fires only if winner crosses threshold)
        jprev = (m >= VTH) ? gi : -1;

        // hard reset uses UNmasked spike: every v >= VTH resets to 0.
        // Skip on the last step: output is exp(pre-reset v).
        if (t < TT - 1) {
#pragma unroll
            for (int j = 0; j < 8; j++)
                if (v[j] >= VTH) v[j] = 0.0f;
        }
    }

    float* op = out + (size_t)w * CC + lane * 8;
    float4 o0 = {expf(v[0]), expf(v[1]), expf(v[2]), expf(v[3])};
    float4 o1 = {expf(v[4]), expf(v[5]), expf(v[6]), expf(v[7])};
    *(float4*)op       = o0;
    *(float4*)(op + 4) = o1;
}

// ---------------------------------------------------------------------------
extern "C" void kernel_launch(void* const* d_in, const int* in_sizes, int n_in,
                              void* d_out, int out_size) {
    const float* x  = (const float*)d_in[0];   // [B, C, T]
    const float* Wf = (const float*)d_in[1];   // [C, C]
    const float* Wr = (const float*)d_in[2];   // [C, C]
    float* out = (float*)d_out;                // [B, C]

    transpose_kernel<<<(CC * CC) / 256, 256>>>(Wf, Wr);

    dim3 gg(CC / 64, TT / 64, BB);             // (4, 8, 2048)
    gemm_kernel<<<gg, 256>>>(x);

    scan_kernel<<<(BB * 32) / 256, 256>>>(out);
}

// round 3
// speedup vs baseline: 1.7157x; 1.7157x over previous
#include <cuda_runtime.h>
#include <cuda_fp16.h>
#include <cstdint>
#include <math.h>

#define BB 2048
#define CC 256
#define TT 512

// ---------------- device scratch (allocations forbidden) ----------------
__device__ float  g_FF[(size_t)BB * TT * CC];   // FF[b][t][i] fp32 (1 GiB)
__device__ __half g_Wfh[CC * CC];               // Wf hi fp16, [i][c] (K-major)
__device__ __half g_Wfl[CC * CC];               // Wf lo fp16
__device__ float  g_WrT[CC * CC];               // WrT[j][i] = Wr[i][j]

// ---------------- helpers ----------------
__device__ __forceinline__ uint32_t smem_u32(const void* p) {
    uint32_t a;
    asm("{ .reg .u64 t; cvta.to.shared.u64 t, %1; cvt.u32.u64 %0, t; }" : "=r"(a) : "l"(p));
    return a;
}

#define LDSM4(R, addr) \
    asm volatile("ldmatrix.sync.aligned.m8n8.x4.shared.b16 {%0,%1,%2,%3}, [%4];" \
        : "=r"((R)[0]), "=r"((R)[1]), "=r"((R)[2]), "=r"((R)[3]) : "r"(addr))

#define LDSM4T(R, addr) \
    asm volatile("ldmatrix.sync.aligned.m8n8.x4.trans.shared.b16 {%0,%1,%2,%3}, [%4];" \
        : "=r"((R)[0]), "=r"((R)[1]), "=r"((R)[2]), "=r"((R)[3]) : "r"(addr))

#define MMA16816(C, A, B) \
    asm volatile("mma.sync.aligned.m16n8k16.row.col.f32.f16.f16.f32 " \
        "{%0,%1,%2,%3}, {%4,%5,%6,%7}, {%8,%9}, {%0,%1,%2,%3};" \
        : "+f"((C)[0]), "+f"((C)[1]), "+f"((C)[2]), "+f"((C)[3]) \
        : "r"((A)[0]), "r"((A)[1]), "r"((A)[2]), "r"((A)[3]), "r"((B)[0]), "r"((B)[1]))

// B tile swizzle ([i][c], 128B rows): XOR bits[6:4] with bits[9:7]
__device__ __forceinline__ uint32_t swzB(uint32_t off) { return off ^ ((off >> 3) & 0x70); }
// A tile swizzle ([c][t], 256B rows): XOR bits[6:4] with bits[10:8]
__device__ __forceinline__ uint32_t swzA(uint32_t off) { return off ^ (((off >> 8) & 7) << 4); }

// ---------------- weight conversion (tiny) ----------------
__global__ void convert_w_kernel(const float* __restrict__ Wf, const float* __restrict__ Wr) {
    int i = blockIdx.x;
    int c = threadIdx.x;
    float w = Wf[i * CC + c];
    __half h = __float2half_rn(w);
    g_Wfh[i * CC + c] = h;
    g_Wfl[i * CC + c] = __float2half_rn(w - __half2float(h));
    g_WrT[c * CC + i] = Wr[i * CC + c];
}

// ---------------- HMMA GEMM: FF[b][t][i] = sum_c x[b][c][t] * Wf[i][c] ----------------
// A = x[b] viewed as [t][c] (fused fp32->fp16 hi/lo split + transpose via smem [c][t]).
// B = Wf [i][c] (K-major). 3 passes: Ah*Bh + Ah*Bl + Al*Bh, fp32 accumulators.
// Block tile: 128(t) x 128(i), K chunks of 64. 8 warps, warp tile 32(t) x 64(i).
#define SMA_HI 0
#define SMA_LO 16384
#define SMB_HI 32768
#define SMB_LO 49152
#define SM_TOTAL 65536

__global__ void __launch_bounds__(256) gemm_mma_kernel(const float* __restrict__ x) {
    extern __shared__ char smem[];
    uint32_t sbase = smem_u32(smem);

    int tid  = threadIdx.x;
    int lane = tid & 31;
    int wid  = tid >> 5;
    int warpM = wid & 3;        // 4 warps along t (32 rows each)
    int warpN = wid >> 2;       // 2 warps along i (64 cols each)

    int i0 = blockIdx.x * 128;
    int t0 = blockIdx.y * 128;
    int b  = blockIdx.z;
    const float* xb = x + (size_t)b * CC * TT;

    float acc[2][8][4];
#pragma unroll
    for (int mf = 0; mf < 2; mf++)
#pragma unroll
        for (int nf = 0; nf < 8; nf++)
#pragma unroll
            for (int e = 0; e < 4; e++) acc[mf][nf][e] = 0.0f;

    // ldmatrix lane-address components (constant over chunks)
    int a_crow = (lane & 7) + ((lane >> 4) << 3);          // c row within 16
    int a_t8   = ((lane >> 3) & 1) * 8;                    // +8 t for matrices 1,3
    int b_irow = (lane & 7) + ((lane >> 4) << 3);          // i row within 16
    int b_c8   = ((lane >> 3) & 1) * 8;                    // +8 c for matrices 1,3

#pragma unroll 1
    for (int c0 = 0; c0 < CC; c0 += 64) {
        if (c0) __syncthreads();

        // --- A tile: x fp32 [c][t-contiguous] -> smem [c][t] fp16 hi/lo, swizzled
#pragma unroll
        for (int it = 0; it < 8; it++) {
            int idx = it * 256 + tid;            // 0..2047
            int c   = idx >> 5;                  // 0..63
            int t4  = idx & 31;                  // 0..31 (float4 index)
            float4 v = *(const float4*)&xb[(size_t)(c0 + c) * TT + t0 + t4 * 4];
            float vv[4] = {v.x, v.y, v.z, v.w};
            uint32_t hp[2], lp[2];
#pragma unroll
            for (int half2i = 0; half2i < 2; half2i++) {
                __half h0 = __float2half_rn(vv[half2i * 2]);
                __half h1 = __float2half_rn(vv[half2i * 2 + 1]);
                __half l0 = __float2half_rn(vv[half2i * 2]     - __half2float(h0));
                __half l1 = __float2half_rn(vv[half2i * 2 + 1] - __half2float(h1));
                hp[half2i] = (uint32_t)__half_as_ushort(h0) | ((uint32_t)__half_as_ushort(h1) << 16);
                lp[half2i] = (uint32_t)__half_as_ushort(l0) | ((uint32_t)__half_as_ushort(l1) << 16);
            }
            uint32_t off = swzA((uint32_t)(c * 256 + t4 * 8));
            *(uint2*)(smem + SMA_HI + off) = make_uint2(hp[0], hp[1]);
            *(uint2*)(smem + SMA_LO + off) = make_uint2(lp[0], lp[1]);
        }

        // --- B tile: Wf hi/lo [i][c] -> smem [i][c] (128B rows), swizzled
#pragma unroll
        for (int it = 0; it < 4; it++) {
            int idx = it * 256 + tid;            // 0..1023 (16B units)
            int i   = idx >> 3;                  // 0..127
            int c16 = idx & 7;                   // 0..7
            uint32_t off = swzB((uint32_t)(i * 128 + c16 * 16));
            size_t src = (size_t)(i0 + i) * CC + c0 + c16 * 8;
            *(uint4*)(smem + SMB_HI + off) = *(const uint4*)(g_Wfh + src);
            *(uint4*)(smem + SMB_LO + off) = *(const uint4*)(g_Wfl + src);
        }
        __syncthreads();

        // --- compute: 4 x k16 steps
#pragma unroll
        for (int k16 = 0; k16 < 4; k16++) {
            uint32_t ah[2][4], al[2][4], bh[8][2], bl[8][2];

            int crow = k16 * 16 + a_crow;
#pragma unroll
            for (int mf = 0; mf < 2; mf++) {
                uint32_t off = swzA((uint32_t)(crow * 256 + (warpM * 32 + mf * 16 + a_t8) * 2));
                LDSM4T(ah[mf], sbase + SMA_HI + off);
                LDSM4T(al[mf], sbase + SMA_LO + off);
            }
            int coff = k16 * 16 + b_c8;
#pragma unroll
            for (int p = 0; p < 4; p++) {
                uint32_t off = swzB((uint32_t)((warpN * 64 + p * 16 + b_irow) * 128 + coff * 2));
                uint32_t r[4];
                LDSM4(r, sbase + SMB_HI + off);
                bh[2 * p][0] = r[0]; bh[2 * p][1] = r[1];
                bh[2 * p + 1][0] = r[2]; bh[2 * p + 1][1] = r[3];
                LDSM4(r, sbase + SMB_LO + off);
                bl[2 * p][0] = r[0]; bl[2 * p][1] = r[1];
                bl[2 * p + 1][0] = r[2]; bl[2 * p + 1][1] = r[3];
            }
#pragma unroll
            for (int mf = 0; mf < 2; mf++)
#pragma unroll
                for (int nf = 0; nf < 8; nf++) {
                    MMA16816(acc[mf][nf], ah[mf], bh[nf]);
                    MMA16816(acc[mf][nf], ah[mf], bl[nf]);
                    MMA16816(acc[mf][nf], al[mf], bh[nf]);
                }
        }
    }

    // --- epilogue: direct STG (quad-lane float2 = full 32B sectors)
    int g   = lane >> 2;
    int t4l = lane & 3;
#pragma unroll
    for (int mf = 0; mf < 2; mf++) {
        int t = t0 + warpM * 32 + mf * 16 + g;
#pragma unroll
        for (int nf = 0; nf < 8; nf++) {
            int i = i0 + warpN * 64 + nf * 8 + t4l * 2;
            float* p0 = g_FF + ((size_t)b * TT + t) * CC + i;
            *(float2*)p0 = make_float2(acc[mf][nf][0], acc[mf][nf][1]);
            *(float2*)(p0 + 8 * CC) = make_float2(acc[mf][nf][2], acc[mf][nf][3]);
        }
    }
}

// ---------------- sequential LIF + WTA scan (one warp per batch row) ----------------
__global__ void __launch_bounds__(256) scan_kernel(float* __restrict__ out) {
    const float DECAY = (float)(1.0 - 1.0 / 6.0);
    const float VTH   = 3.0f;

    int w    = (int)((blockIdx.x * blockDim.x + threadIdx.x) >> 5);
    int lane = threadIdx.x & 31;
    if (w >= BB) return;

    const float* ffb = g_FF + (size_t)w * TT * CC + lane * 8;

    float v[8];
#pragma unroll
    for (int j = 0; j < 8; j++) v[j] = 0.0f;

    int jprev = -1;

    for (int t = 0; t < TT; t++) {
        float4 f0 = *(const float4*)(ffb + (size_t)t * CC);
        float4 f1 = *(const float4*)(ffb + (size_t)t * CC + 4);
        float f[8] = {f0.x, f0.y, f0.z, f0.w, f1.x, f1.y, f1.z, f1.w};

        if (jprev >= 0) {
            const float4* wp = (const float4*)(g_WrT + jprev * CC + lane * 8);
            float4 r0 = wp[0];
            float4 r1 = wp[1];
            f[0] += r0.x; f[1] += r0.y; f[2] += r0.z; f[3] += r0.w;
            f[4] += r1.x; f[5] += r1.y; f[6] += r1.z; f[7] += r1.w;
        }

#pragma unroll
        for (int j = 0; j < 8; j++) v[j] = v[j] * DECAY + f[j];

        float m = v[0];
        int   mi = 0;
#pragma unroll
        for (int j = 1; j < 8; j++)
            if (v[j] > m) { m = v[j]; mi = j; }
        int gi = lane * 8 + mi;
#pragma unroll
        for (int off = 16; off > 0; off >>= 1) {
            float om = __shfl_xor_sync(0xFFFFFFFFu, m,  off);
            int   oi = __shfl_xor_sync(0xFFFFFFFFu, gi, off);
            if (om > m || (om == m && oi < gi)) { m = om; gi = oi; }
        }

        jprev = (m >= VTH) ? gi : -1;

        if (t < TT - 1) {
#pragma unroll
            for (int j = 0; j < 8; j++)
                if (v[j] >= VTH) v[j] = 0.0f;
        }
    }

    float* op = out + (size_t)w * CC + lane * 8;
    float4 o0 = {expf(v[0]), expf(v[1]), expf(v[2]), expf(v[3])};
    float4 o1 = {expf(v[4]), expf(v[5]), expf(v[6]), expf(v[7])};
    *(float4*)op       = o0;
    *(float4*)(op + 4) = o1;
}

// ---------------------------------------------------------------------------
extern "C" void kernel_launch(void* const* d_in, const int* in_sizes, int n_in,
                              void* d_out, int out_size) {
    const float* x  = (const float*)d_in[0];
    const float* Wf = (const float*)d_in[1];
    const float* Wr = (const float*)d_in[2];
    float* out = (float*)d_out;

    cudaFuncSetAttribute(gemm_mma_kernel, cudaFuncAttributeMaxDynamicSharedMemorySize, SM_TOTAL);

    convert_w_kernel<<<CC, CC>>>(Wf, Wr);
    gemm_mma_kernel<<<dim3(CC / 128, TT / 128, BB), 256, SM_TOTAL>>>(x);
    scan_kernel<<<(BB * 32) / 256, 256>>>(out);
}

// round 4
// speedup vs baseline: 2.6232x; 1.5289x over previous
#include <cuda_runtime.h>
#include <cuda_fp16.h>
#include <cstdint>
#include <math.h>

#define BB 2048
#define CC 256
#define TT 512

// ---------------- device scratch (allocations forbidden) ----------------
__device__ float  g_FF[(size_t)BB * TT * CC];   // FF[b][t][i] fp32 (1 GiB)
__device__ __half g_Wfh[CC * CC];               // Wf hi fp16, [i][c] (K-major)
__device__ __half g_Wfl[CC * CC];               // Wf lo fp16
__device__ float  g_WrT[CC * CC];               // WrT[j][i] = Wr[i][j]

// ---------------- helpers ----------------
__device__ __forceinline__ uint32_t smem_u32(const void* p) {
    uint32_t a;
    asm("{ .reg .u64 t; cvta.to.shared.u64 t, %1; cvt.u32.u64 %0, t; }" : "=r"(a) : "l"(p));
    return a;
}

#define LDSM4(R, addr) \
    asm volatile("ldmatrix.sync.aligned.m8n8.x4.shared.b16 {%0,%1,%2,%3}, [%4];" \
        : "=r"((R)[0]), "=r"((R)[1]), "=r"((R)[2]), "=r"((R)[3]) : "r"(addr))

#define LDSM4T(R, addr) \
    asm volatile("ldmatrix.sync.aligned.m8n8.x4.trans.shared.b16 {%0,%1,%2,%3}, [%4];" \
        : "=r"((R)[0]), "=r"((R)[1]), "=r"((R)[2]), "=r"((R)[3]) : "r"(addr))

#define MMA16816(C, A, B) \
    asm volatile("mma.sync.aligned.m16n8k16.row.col.f32.f16.f16.f32 " \
        "{%0,%1,%2,%3}, {%4,%5,%6,%7}, {%8,%9}, {%0,%1,%2,%3};" \
        : "+f"((C)[0]), "+f"((C)[1]), "+f"((C)[2]), "+f"((C)[3]) \
        : "r"((A)[0]), "r"((A)[1]), "r"((A)[2]), "r"((A)[3]), "r"((B)[0]), "r"((B)[1]))

#define CP_ASYNC16(dst, src) \
    asm volatile("cp.async.cg.shared.global [%0], [%1], 16;" :: "r"(dst), "l"(src))
#define CP_COMMIT() asm volatile("cp.async.commit_group;" ::: "memory")
#define CP_WAIT(N)  asm volatile("cp.async.wait_group %0;" :: "n"(N) : "memory")

// B tile swizzle ([i][c], 128B rows): XOR bits[6:4] with bits[9:7]
__device__ __forceinline__ uint32_t swzB(uint32_t off) { return off ^ ((off >> 3) & 0x70); }
// A tile swizzle ([c][t], 256B rows): XOR bits[6:4] with bits[10:8]
__device__ __forceinline__ uint32_t swzA(uint32_t off) { return off ^ (((off >> 8) & 7) << 4); }

// ---------------- weight conversion (tiny) ----------------
__global__ void convert_w_kernel(const float* __restrict__ Wf, const float* __restrict__ Wr) {
    int i = blockIdx.x;
    int c = threadIdx.x;
    float w = Wf[i * CC + c];
    __half h = __float2half_rn(w);
    g_Wfh[i * CC + c] = h;
    g_Wfl[i * CC + c] = __float2half_rn(w - __half2float(h));
    g_WrT[c * CC + i] = Wr[i * CC + c];
}

// ---------------- HMMA GEMM: FF[b][t][i] = sum_c x[b][c][t] * Wf[i][c] ----------------
// Block tile 128(t) x 128(i), K chunks of 64, double-buffered smem.
// 16 warps, warp tile 32(t) x 32(i). 3 passes: Ah*Bh + Ah*Bl + Al*Bh.
// Per-stage smem: A_HI 16K | A_LO 16K | B_HI 16K | B_LO 16K  (64KB); 2 stages.
#define STG_SZ  65536
#define OFF_AH  0
#define OFF_AL  16384
#define OFF_BH  32768
#define OFF_BL  49152
#define SM_TOTAL (2 * STG_SZ)

__global__ void __launch_bounds__(512, 1) gemm_mma_kernel(const float* __restrict__ x) {
    extern __shared__ char smem[];
    uint32_t sbase = smem_u32(smem);

    int tid  = threadIdx.x;
    int lane = tid & 31;
    int wid  = tid >> 5;
    int warpM = wid & 3;        // 4 warps along t (32 rows each)
    int warpN = wid >> 2;       // 4 warps along i (32 cols each)

    int i0 = blockIdx.x * 128;
    int t0 = blockIdx.y * 128;
    int b  = blockIdx.z;
    const float* xb = x + (size_t)b * CC * TT;

    float acc[2][4][4];
#pragma unroll
    for (int mf = 0; mf < 2; mf++)
#pragma unroll
        for (int nf = 0; nf < 4; nf++)
#pragma unroll
            for (int e = 0; e < 4; e++) acc[mf][nf][e] = 0.0f;

    // load indices (constant across chunks)
    int a_c  = tid >> 5;        // base c row for A loads (+128 for second half... see loop)
    int a_t4 = tid & 31;        // float4 index along t
    int b_i  = tid >> 3;        // i row for B cp.async (+64 in 2nd iter)
    int b_c16 = tid & 7;        // 16B col chunk

    // ldmatrix lane-address components
    int a_crow = (lane & 7) + ((lane >> 4) << 3);
    int a_t8   = ((lane >> 3) & 1) * 8;
    int b_irow = (lane & 7) + ((lane >> 4) << 3);
    int b_c8   = ((lane >> 3) & 1) * 8;

    float4 av[4];

    // helper lambdas via macros
#define LOAD_A_REGS(kc) do { \
    _Pragma("unroll") \
    for (int it = 0; it < 4; it++) \
        av[it] = *(const float4*)&xb[(size_t)((kc) + a_c + it * 16) * TT + t0 + a_t4 * 4]; \
} while (0)

#define STS_A(stage) do { \
    _Pragma("unroll") \
    for (int it = 0; it < 4; it++) { \
        float vv[4] = {av[it].x, av[it].y, av[it].z, av[it].w}; \
        uint32_t hp[2], lp[2]; \
        _Pragma("unroll") \
        for (int q = 0; q < 2; q++) { \
            __half h0 = __float2half_rn(vv[q * 2]); \
            __half h1 = __float2half_rn(vv[q * 2 + 1]); \
            __half l0 = __float2half_rn(vv[q * 2]     - __half2float(h0)); \
            __half l1 = __float2half_rn(vv[q * 2 + 1] - __half2float(h1)); \
            hp[q] = (uint32_t)__half_as_ushort(h0) | ((uint32_t)__half_as_ushort(h1) << 16); \
            lp[q] = (uint32_t)__half_as_ushort(l0) | ((uint32_t)__half_as_ushort(l1) << 16); \
        } \
        uint32_t off = swzA((uint32_t)((a_c + it * 16) * 256 + a_t4 * 8)); \
        *(uint2*)(smem + (stage) * STG_SZ + OFF_AH + off) = make_uint2(hp[0], hp[1]); \
        *(uint2*)(smem + (stage) * STG_SZ + OFF_AL + off) = make_uint2(lp[0], lp[1]); \
    } \
} while (0)

#define CPA_B(kc, stage) do { \
    _Pragma("unroll") \
    for (int it = 0; it < 2; it++) { \
        int i = b_i + it * 64; \
        uint32_t off = swzB((uint32_t)(i * 128 + b_c16 * 16)); \
        const __half* srch = g_Wfh + (size_t)(i0 + i) * CC + (kc) + b_c16 * 8; \
        const __half* srcl = g_Wfl + (size_t)(i0 + i) * CC + (kc) + b_c16 * 8; \
        CP_ASYNC16(sbase + (stage) * STG_SZ + OFF_BH + off, srch); \
        CP_ASYNC16(sbase + (stage) * STG_SZ + OFF_BL + off, srcl); \
    } \
    CP_COMMIT(); \
} while (0)

    // ---- prologue: stage 0 ----
    CPA_B(0, 0);
    LOAD_A_REGS(0);
    STS_A(0);

#pragma unroll
    for (int k = 0; k < 4; k++) {
        int stage = k & 1;
        CP_WAIT(0);              // my B group for chunk k complete
        __syncthreads();         // all threads' STS(A,k) + cp.async(B,k) visible

        if (k < 3) {             // issue next chunk loads (overlap with compute)
            CPA_B((k + 1) * 64, stage ^ 1);
            LOAD_A_REGS((k + 1) * 64);
        }

        // ---- compute chunk k from stage ----
        uint32_t abase = sbase + stage * STG_SZ;
#pragma unroll
        for (int k16 = 0; k16 < 4; k16++) {
            uint32_t ah[2][4], al[2][4], bh[4][2], bl[4][2];
            int crow = k16 * 16 + a_crow;
#pragma unroll
            for (int mf = 0; mf < 2; mf++) {
                uint32_t off = swzA((uint32_t)(crow * 256 + (warpM * 32 + mf * 16 + a_t8) * 2));
                LDSM4T(ah[mf], abase + OFF_AH + off);
                LDSM4T(al[mf], abase + OFF_AL + off);
            }
            int coff = k16 * 16 + b_c8;
#pragma unroll
            for (int p = 0; p < 2; p++) {
                uint32_t off = swzB((uint32_t)((warpN * 32 + p * 16 + b_irow) * 128 + coff * 2));
                uint32_t r[4];
                LDSM4(r, abase + OFF_BH + off);
                bh[2 * p][0] = r[0]; bh[2 * p][1] = r[1];
                bh[2 * p + 1][0] = r[2]; bh[2 * p + 1][1] = r[3];
                LDSM4(r, abase + OFF_BL + off);
                bl[2 * p][0] = r[0]; bl[2 * p][1] = r[1];
                bl[2 * p + 1][0] = r[2]; bl[2 * p + 1][1] = r[3];
            }
#pragma unroll
            for (int mf = 0; mf < 2; mf++)
#pragma unroll
                for (int nf = 0; nf < 4; nf++) {
                    MMA16816(acc[mf][nf], ah[mf], bh[nf]);
                    MMA16816(acc[mf][nf], ah[mf], bl[nf]);
                    MMA16816(acc[mf][nf], al[mf], bh[nf]);
                }
        }

        if (k < 3) STS_A(stage ^ 1);
    }

    // ---- epilogue: direct STG (quad-lane float2 = full 32B sectors) ----
    int g   = lane >> 2;
    int t4l = lane & 3;
#pragma unroll
    for (int mf = 0; mf < 2; mf++) {
        int t = t0 + warpM * 32 + mf * 16 + g;
#pragma unroll
        for (int nf = 0; nf < 4; nf++) {
            int i = i0 + warpN * 32 + nf * 8 + t4l * 2;
            float* p0 = g_FF + ((size_t)b * TT + t) * CC + i;
            *(float2*)p0 = make_float2(acc[mf][nf][0], acc[mf][nf][1]);
            *(float2*)(p0 + 8 * CC) = make_float2(acc[mf][nf][2], acc[mf][nf][3]);
        }
    }
}

// ---------------- sequential LIF + WTA scan (one warp per batch row) ----------------
__global__ void __launch_bounds__(256) scan_kernel(float* __restrict__ out) {
    const float DECAY = (float)(1.0 - 1.0 / 6.0);
    const float VTH   = 3.0f;
    const int   KEY_VTH = 0x40400000;   // order-preserving int key of +3.0f

    int w    = (int)((blockIdx.x * blockDim.x + threadIdx.x) >> 5);
    int lane = threadIdx.x & 31;
    if (w >= BB) return;

    const float* ffb = g_FF + (size_t)w * TT * CC + lane * 8;

    float v[8], f[8], wr[8];
#pragma unroll
    for (int j = 0; j < 8; j++) v[j] = 0.0f;
    bool has_r = false;

    {   // preload f(0)
        float4 f0 = *(const float4*)(ffb);
        float4 f1 = *(const float4*)(ffb + 4);
        f[0]=f0.x; f[1]=f0.y; f[2]=f0.z; f[3]=f0.w;
        f[4]=f1.x; f[5]=f1.y; f[6]=f1.z; f[7]=f1.w;
    }

    for (int t = 0; t < TT - 1; t++) {
        // prefetch next timestep's FF (independent of this step's chain)
        float4 n0 = *(const float4*)(ffb + (size_t)(t + 1) * CC);
        float4 n1 = *(const float4*)(ffb + (size_t)(t + 1) * CC + 4);

        // LIF charge
        if (has_r) {
#pragma unroll
            for (int j = 0; j < 8; j++) v[j] = v[j] * DECAY + f[j] + wr[j];
        } else {
#pragma unroll
            for (int j = 0; j < 8; j++) v[j] = v[j] * DECAY + f[j];
        }

        // local argmax (first occurrence)
        float m = v[0];
        int   mi = 0;
#pragma unroll
        for (int j = 1; j < 8; j++)
            if (v[j] > m) { m = v[j]; mi = j; }

        // warp argmax via redux on order-preserving key
        int s = __float_as_int(m);
        int key = s ^ ((s >> 31) & 0x7fffffff);
        int kmax;
        asm volatile("redux.sync.max.s32 %0, %1, 0xffffffff;" : "=r"(kmax) : "r"(key));
        unsigned ball = __ballot_sync(0xffffffffu, key == kmax);
        int src = __ffs(ball) - 1;
        int gi  = __shfl_sync(0xffffffffu, lane * 8 + mi, src);

        bool fired = (kmax >= KEY_VTH);
        if (fired) {   // issue WrT gather early; consumed next iteration
            const float4* wp = (const float4*)(g_WrT + gi * CC + lane * 8);
            float4 r0 = wp[0];
            float4 r1 = wp[1];
            wr[0]=r0.x; wr[1]=r0.y; wr[2]=r0.z; wr[3]=r0.w;
            wr[4]=r1.x; wr[5]=r1.y; wr[6]=r1.z; wr[7]=r1.w;
        }
        has_r = fired;

        // hard reset (unmasked spike)
#pragma unroll
        for (int j = 0; j < 8; j++)
            if (v[j] >= VTH) v[j] = 0.0f;

        f[0]=n0.x; f[1]=n0.y; f[2]=n0.z; f[3]=n0.w;
        f[4]=n1.x; f[5]=n1.y; f[6]=n1.z; f[7]=n1.w;
    }

    // final step: charge only (output is exp(pre-reset v))
    if (has_r) {
#pragma unroll
        for (int j = 0; j < 8; j++) v[j] = v[j] * DECAY + f[j] + wr[j];
    } else {
#pragma unroll
        for (int j = 0; j < 8; j++) v[j] = v[j] * DECAY + f[j];
    }

    float* op = out + (size_t)w * CC + lane * 8;
    float4 o0 = {expf(v[0]), expf(v[1]), expf(v[2]), expf(v[3])};
    float4 o1 = {expf(v[4]), expf(v[5]), expf(v[6]), expf(v[7])};
    *(float4*)op       = o0;
    *(float4*)(op + 4) = o1;
}

// ---------------------------------------------------------------------------
extern "C" void kernel_launch(void* const* d_in, const int* in_sizes, int n_in,
                              void* d_out, int out_size) {
    const float* x  = (const float*)d_in[0];
    const float* Wf = (const float*)d_in[1];
    const float* Wr = (const float*)d_in[2];
    float* out = (float*)d_out;

    cudaFuncSetAttribute(gemm_mma_kernel, cudaFuncAttributeMaxDynamicSharedMemorySize, SM_TOTAL);

    convert_w_kernel<<<CC, CC>>>(Wf, Wr);
    gemm_mma_kernel<<<dim3(CC / 128, TT / 128, BB), 512, SM_TOTAL>>>(x);
    scan_kernel<<<(BB * 32) / 256, 256>>>(out);
}